// round 7
// baseline (speedup 1.0000x reference)
#include <cuda_runtime.h>
#include <cstdint>
#include <cstddef>

#define T_STEPS 1024
#define BATCH   128
#define INDIM   100
#define HID     200
#define NCLS    100
#define NBG     8           // batch groups
#define MB      16          // batch per group
#define NHG     17          // hidden groups per batch group
#define NHU     12          // hidden units per CTA
#define NG      48          // gate rows per CTA
#define NTHR    512
#define NCTA    (NBG*NHG)   // 136
#define XSTR    20          // smem stride of [k][b] staging buffer
#define W1ST    404         // padded W1 row stride (bank-conflict-free)

#define HN_OFF  (T_STEPS*BATCH*NCLS)
#define CN_OFF  (HN_OFF + 2*BATCH*HID)

// ---- smem float offsets ----
#define OFF_W0  0                        // [NG][300]
#define OFF_W1  14400                    // [NG][404]
#define OFF_XH  33792                    // [500][XSTR]
#define OFF_GB0 43792                    // [4][NG][MB]
#define OFF_GB1 46864                    // [8][NG][MB]
#define OFF_XA  53008                    // [2][NG][MB]
#define OFF_B0  54544
#define OFF_B1  54592
#define OFF_C0  54640                    // [NHU][MB]
#define OFF_C1  54832
#define SMEM_FLOATS 55040
#define SMEM_BYTES  (SMEM_FLOATS*4)      // 220,160 B

// FC-phase smem reuse
#define OFF_FW  0        // [100][200]
#define OFF_FB  20000
#define OFF_YS  20128    // [50][128]

// -------- device scratch --------
__device__ __align__(256) float g_ph0[2][HID*BATCH];
__device__ __align__(256) float g_ph1[2][HID*BATCH];
__device__ __align__(256) float g_y1[(size_t)T_STEPS*HID*BATCH];
__device__ unsigned g_bar[NBG*32];
__device__ unsigned g_gbar;
__device__ unsigned g_ack;

__device__ __forceinline__ float sigm(float x) {
    return __fdividef(1.0f, 1.0f + __expf(-x));
}
__device__ __forceinline__ float tanha(float x) {
    return fmaf(2.0f, sigm(2.0f * x), -1.0f);
}

__device__ __forceinline__ void bar_arrive(unsigned* p) {
    unsigned one = 1u;
    asm volatile("red.release.gpu.global.add.u32 [%0], %1;" :: "l"(p), "r"(one) : "memory");
}
__device__ __forceinline__ unsigned ld_acq(const unsigned* p) {
    unsigned v;
    asm volatile("ld.acquire.gpu.global.u32 %0, [%1];" : "=r"(v) : "l"(p) : "memory");
    return v;
}
__device__ __forceinline__ void cpa16(uint32_t dst, const void* src) {
    asm volatile("cp.async.cg.shared.global [%0], [%1], 16;" :: "r"(dst), "l"(src) : "memory");
}
__device__ __forceinline__ void cpa_wait() {
    asm volatile("cp.async.commit_group;\n\tcp.async.wait_group 0;" ::: "memory");
}

// packed f32x2 helpers
#define FMA2(acc, w, x) \
    asm("fma.rn.f32x2 %0, %1, %2, %0;" : "+l"(acc) : "l"(w), "l"(x))
__device__ __forceinline__ unsigned long long dup2(float s) {
    unsigned long long d;
    asm("mov.b64 %0, {%1, %1};" : "=l"(d) : "f"(s));
    return d;
}

// gates[r0..r0+2][bq..bq+3] partial over k-chunk ks of length KH.
// Batch-pair f32x2: x LDS.128 yields two {b,b+1} pairs directly; W scalars
// duplicated into {w,w} register pairs (alu-pipe MOVs, fma-pipe load halved).
template<int KH, int WST>
__device__ __forceinline__ void gate_mm4(const float* __restrict__ W,
                                         const float* __restrict__ xp0,
                                         float* __restrict__ gbuf,
                                         int r0, int bq, int ks)
{
    const float* w0 = W + r0 * WST + ks * KH;
    const float* w1 = w0 + WST;
    const float* w2 = w1 + WST;
    const float* xp = xp0 + ks * KH * XSTR + bq;
    unsigned long long a0p0=0ull, a0p1=0ull;   // row r0:   batches {bq,bq+1},{bq+2,bq+3}
    unsigned long long a1p0=0ull, a1p1=0ull;   // row r0+1
    unsigned long long a2p0=0ull, a2p1=0ull;   // row r0+2
    #pragma unroll 5
    for (int k = 0; k < KH; k += 2) {
        ulonglong2 xa = *(const ulonglong2*)(xp + k * XSTR);        // k:   {b0,b1},{b2,b3}
        ulonglong2 xb = *(const ulonglong2*)(xp + (k + 1) * XSTR);  // k+1
        float2 wa = *(const float2*)(w0 + k);
        float2 wb = *(const float2*)(w1 + k);
        float2 wc = *(const float2*)(w2 + k);
        unsigned long long wax = dup2(wa.x), wbx = dup2(wb.x), wcx = dup2(wc.x);
        FMA2(a0p0, wax, xa.x); FMA2(a0p1, wax, xa.y);
        FMA2(a1p0, wbx, xa.x); FMA2(a1p1, wbx, xa.y);
        FMA2(a2p0, wcx, xa.x); FMA2(a2p1, wcx, xa.y);
        unsigned long long way = dup2(wa.y), wby = dup2(wb.y), wcy = dup2(wc.y);
        FMA2(a0p0, way, xb.x); FMA2(a0p1, way, xb.y);
        FMA2(a1p0, wby, xb.x); FMA2(a1p1, wby, xb.y);
        FMA2(a2p0, wcy, xb.x); FMA2(a2p1, wcy, xb.y);
    }
    float* g = gbuf + ks * (NG * MB);
    *(ulonglong2*)(g + (r0+0)*MB + bq) = make_ulonglong2(a0p0, a0p1);
    *(ulonglong2*)(g + (r0+1)*MB + bq) = make_ulonglong2(a1p0, a1p1);
    *(ulonglong2*)(g + (r0+2)*MB + bq) = make_ulonglong2(a2p0, a2p1);
}

__global__ void __launch_bounds__(NTHR, 1)
lstm_all_kernel(const float* __restrict__ inp,  const float* __restrict__ h0in,
                const float* __restrict__ c0in,
                const float* __restrict__ Wih0, const float* __restrict__ Whh0,
                const float* __restrict__ bih0, const float* __restrict__ bhh0,
                const float* __restrict__ Wih1, const float* __restrict__ Whh1,
                const float* __restrict__ bih1, const float* __restrict__ bhh1,
                const float* __restrict__ fcW,  const float* __restrict__ fcb,
                float* __restrict__ out)
{
    extern __shared__ float sm[];
    float* W0s   = sm + OFF_W0;
    float* W1s   = sm + OFF_W1;
    float* xh    = sm + OFF_XH;
    float* gb0   = sm + OFF_GB0;
    float* gb1   = sm + OFF_GB1;
    float* xac   = sm + OFF_XA;
    float* bias0 = sm + OFF_B0;
    float* bias1 = sm + OFF_B1;
    float* c0s   = sm + OFF_C0;
    float* c1s   = sm + OFF_C1;

    const int tid = threadIdx.x;
    const int bg  = blockIdx.x / NHG;
    const int hg  = blockIdx.x % NHG;
    const int b0  = bg * MB;
    const int hs  = hg * NHU;
    const uint32_t smb = (uint32_t)__cvta_generic_to_shared(sm);

    // mm decode: cell in 0..63 -> 16 row-groups x 4 batch-quads; ksplit = tid>>6
    const int cell = tid & 63;
    const int bq   = (cell & 3) * 4;
    const int r0   = (cell >> 2) * 3;
    const int ksp  = tid >> 6;            // 0..7

    // ---- resident weight slices ----
    for (int i = tid; i < NG * 300; i += NTHR) {
        int c = i / 300, k = i - c * 300;
        int gate = c / NHU, u = c - gate * NHU;
        int j = hs + u, row = gate * HID + j;
        float v = 0.f;
        if (j < HID) v = (k < INDIM) ? Wih0[row * INDIM + k] : Whh0[row * HID + (k - INDIM)];
        W0s[c * 300 + k] = v;
    }
    for (int i = tid; i < NG * 400; i += NTHR) {
        int c = i / 400, k = i - c * 400;
        int gate = c / NHU, u = c - gate * NHU;
        int j = hs + u, row = gate * HID + j;
        float v = 0.f;
        if (j < HID) v = (k < HID) ? Wih1[row * HID + k] : Whh1[row * HID + (k - HID)];
        W1s[c * W1ST + k] = v;
    }
    if (tid < NG) {
        int gate = tid / NHU, u = tid - gate * NHU;
        int j = hs + u, row = gate * HID + j;
        bias0[tid] = (j < HID) ? bih0[row] + bhh0[row] : 0.f;
        bias1[tid] = (j < HID) ? bih1[row] + bhh1[row] : 0.f;
    }

    // ---- init c state, publish initial h ----
    if (tid < NHU * MB) {
        int e = tid, u = e >> 4, b = e & 15, j = hs + u;
        float cv0 = 0.f, cv1 = 0.f;
        if (j < HID) {
            cv0 = c0in[(b0 + b) * HID + j];
            cv1 = c0in[BATCH * HID + (b0 + b) * HID + j];
            g_ph0[1][j * BATCH + b0 + b] = h0in[(b0 + b) * HID + j];
            g_ph1[0][j * BATCH + b0 + b] = h0in[BATCH * HID + (b0 + b) * HID + j];
        }
        c0s[e] = cv0;
        c1s[e] = cv1;
    }

    // ---- prologue: stage x(0), xacc(0) ----
    {
        const float* xsrc = inp + (size_t)b0 * INDIM;
        for (int idx = tid; idx < MB * INDIM; idx += NTHR) {
            int b = idx / INDIM, k = idx - b * INDIM;
            xh[k * XSTR + b] = __ldg(xsrc + b * INDIM + k);
        }
    }
    __syncthreads();
    if (tid < 128) gate_mm4<50, 300>(W0s, xh, xac, r0, bq, ksp);
    __syncthreads();

    unsigned* gbar = &g_bar[bg * 32];
    unsigned ep = 1;
    if (tid == 0) {
        bar_arrive(gbar);
        while (ld_acq(gbar) < ep * NHG) {}
    }
    __syncthreads();

    // ---- main loop: iter it = layer0(step it) + layer1(step it-1) ----
    for (int it = 0; it <= T_STEPS; ++it) {
        // async-stage h0(it-1) -> rows 100-299, h1(it-2) -> rows 300-499
        {
            const float* ph0 = g_ph0[(it + 1) & 1];
            const float* ph1 = g_ph1[(it + 1) & 1];
            int tot = (it >= 1) ? 1600 : 800;
            for (int idx = tid; idx < tot; idx += NTHR) {
                int a = idx >> 2, q = idx & 3;          // a in 0..399 over [h0;h1]
                const float* src = (a < HID) ? (ph0 + a * BATCH)
                                             : (ph1 + (a - HID) * BATCH);
                cpa16(smb + (OFF_XH + (INDIM + a) * XSTR + q * 4) * 4,
                      src + b0 + q * 4);
            }
            cpa_wait();
        }
        __syncthreads();

        if (it < T_STEPS && tid < 256)
            gate_mm4<50, 300>(W0s + INDIM, xh + INDIM * XSTR, gb0, r0, bq, ksp); // Whh0
        if (it >= 1)
            gate_mm4<50, W1ST>(W1s, xh + INDIM * XSTR, gb1, r0, bq, ksp);        // layer1 full
        __syncthreads();

        // ---- pointwise (layer0 on t<192, layer1 on 192<=t<384) ----
        if (it < T_STEPS && tid < 192) {
            int e = tid, u = e >> 4, b = e & 15, j = hs + u;
            float gv[4];
            #pragma unroll
            for (int g = 0; g < 4; ++g) {
                int rr = g * NHU + u;
                float v = bias0[rr];
                #pragma unroll
                for (int s = 0; s < 4; ++s) v += gb0[s * (NG*MB) + rr * MB + b];
                v += xac[rr * MB + b] + xac[NG*MB + rr * MB + b];
                gv[g] = v;
            }
            float c = c0s[e];
            c = sigm(gv[1]) * c + sigm(gv[0]) * tanha(gv[2]);
            float h = sigm(gv[3]) * tanha(c);
            c0s[e] = c;
            if (j < HID) g_ph0[it & 1][j * BATCH + b0 + b] = h;
        }
        if (it >= 1 && tid >= 192 && tid < 384) {
            int e = tid - 192, u = e >> 4, b = e & 15, j = hs + u;
            float gv[4];
            #pragma unroll
            for (int g = 0; g < 4; ++g) {
                int rr = g * NHU + u;
                float v = bias1[rr];
                #pragma unroll
                for (int s = 0; s < 8; ++s) v += gb1[s * (NG*MB) + rr * MB + b];
                gv[g] = v;
            }
            float c = c1s[e];
            c = sigm(gv[1]) * c + sigm(gv[0]) * tanha(gv[2]);
            float h = sigm(gv[3]) * tanha(c);
            c1s[e] = c;
            if (j < HID) {
                g_ph1[it & 1][j * BATCH + b0 + b] = h;
                g_y1[(size_t)(it - 1) * HID * BATCH + j * BATCH + b0 + b] = h;
            }
        }
        if (it == T_STEPS) break;
        __syncthreads();

        ep++;
        if (tid == 0) bar_arrive(gbar);

        // ---- barrier-shadow: stage x(it+1), xacc(it+1) ----
        if (it + 1 < T_STEPS) {
            const float* xsrc = inp + (size_t)(it + 1) * BATCH * INDIM + (size_t)b0 * INDIM;
            for (int idx = tid; idx < MB * INDIM; idx += NTHR) {
                int b = idx / INDIM, k = idx - b * INDIM;
                xh[k * XSTR + b] = __ldg(xsrc + b * INDIM + k);
            }
            __syncthreads();
            if (tid < 128) gate_mm4<50, 300>(W0s, xh, xac, r0, bq, ksp);
        }

        if (tid == 0) { while (ld_acq(gbar) < ep * NHG) {} }
        __syncthreads();
    }

    // Final layer1 pointwise (tid 192-383) must be visible to epilogue readers.
    __syncthreads();

    // ---- epilogue: hn, cn ----
    if (tid < NHU * MB) {
        int e = tid, u = e >> 4, b = e & 15, j = hs + u;
        if (j < HID) {
            out[HN_OFF + (b0 + b) * HID + j]               = __ldcg(&g_ph0[(T_STEPS - 1) & 1][j * BATCH + b0 + b]);
            out[HN_OFF + BATCH * HID + (b0 + b) * HID + j] = __ldcg(&g_ph1[T_STEPS & 1][j * BATCH + b0 + b]);
            out[CN_OFF + (b0 + b) * HID + j]               = c0s[e];
            out[CN_OFF + BATCH * HID + (b0 + b) * HID + j] = c1s[e];
        }
    }
    __syncthreads();

    // ---- global barrier before FC ----
    if (tid == 0) {
        bar_arrive(&g_gbar);
        while (ld_acq(&g_gbar) < NCTA) {}
    }
    __syncthreads();

    // ---- FC phase: out[t,b,c] = fcb[c] + sum_h fcW[c][h] * y1[t,h,b] ----
    {
        float* fws = sm + OFF_FW;
        float* fbs = sm + OFF_FB;
        float* ys  = sm + OFF_YS;
        for (int i = tid; i < NCLS * HID; i += NTHR) fws[i] = fcW[i];
        if (tid < NCLS) fbs[tid] = fcb[tid];
        __syncthreads();

        const int bqf = (tid & 31) * 4;
        const int cg  = tid >> 5;              // 0..15
        for (int tt = 0; tt < 8; ++tt) {
            int t = blockIdx.x * 8 + tt;
            if (t >= T_STEPS) break;
            const float* y = g_y1 + (size_t)t * HID * BATCH;
            float acc[2][4][4];
            #pragma unroll
            for (int qi = 0; qi < 2; qi++) {
                int cq = cg + 16 * qi;
                #pragma unroll
                for (int jc = 0; jc < 4; jc++) {
                    float bv = (cq < 25) ? fbs[cq * 4 + jc] : 0.f;
                    #pragma unroll
                    for (int jb = 0; jb < 4; jb++) acc[qi][jc][jb] = bv;
                }
            }
            for (int kc = 0; kc < 4; ++kc) {
                __syncthreads();
                for (int i = tid; i < 50 * 32; i += NTHR) {
                    int k = i >> 5, q = i & 31;
                    *(float4*)&ys[k * 128 + q * 4] =
                        __ldcg((const float4*)(y + (size_t)(kc * 50 + k) * BATCH + q * 4));
                }
                __syncthreads();
                for (int k = 0; k < 50; ++k) {
                    float4 yv = *(const float4*)&ys[k * 128 + bqf];
                    #pragma unroll
                    for (int qi = 0; qi < 2; qi++) {
                        int cq = cg + 16 * qi;
                        if (cq < 25) {
                            #pragma unroll
                            for (int jc = 0; jc < 4; jc++) {
                                float w = fws[(cq * 4 + jc) * HID + kc * 50 + k];
                                acc[qi][jc][0] = fmaf(w, yv.x, acc[qi][jc][0]);
                                acc[qi][jc][1] = fmaf(w, yv.y, acc[qi][jc][1]);
                                acc[qi][jc][2] = fmaf(w, yv.z, acc[qi][jc][2]);
                                acc[qi][jc][3] = fmaf(w, yv.w, acc[qi][jc][3]);
                            }
                        }
                    }
                }
            }
            float* o = out + (size_t)t * BATCH * NCLS;
            #pragma unroll
            for (int qi = 0; qi < 2; qi++) {
                int cq = cg + 16 * qi;
                if (cq < 25) {
                    #pragma unroll
                    for (int jb = 0; jb < 4; jb++) {
                        float4 v = make_float4(acc[qi][0][jb], acc[qi][1][jb],
                                               acc[qi][2][jb], acc[qi][3][jb]);
                        *(float4*)(o + (bqf + jb) * NCLS + cq * 4) = v;
                    }
                }
            }
        }
    }

    // ---- reset-free counter cleanup ----
    __syncthreads();
    if (tid == 0) {
        bar_arrive(&g_ack);
        if (blockIdx.x == 0) {
            while (ld_acq(&g_ack) < NCTA) {}
            for (int i = 0; i < NBG; i++) *(volatile unsigned*)&g_bar[i * 32] = 0u;
            *(volatile unsigned*)&g_gbar = 0u;
            *(volatile unsigned*)&g_ack  = 0u;
        }
    }
}

extern "C" void kernel_launch(void* const* d_in, const int* in_sizes, int n_in,
                              void* d_out, int out_size)
{
    (void)in_sizes; (void)n_in; (void)out_size;
    const float* inp  = (const float*)d_in[0];
    const float* h0   = (const float*)d_in[1];
    const float* c0   = (const float*)d_in[2];
    const float* Wih0 = (const float*)d_in[3];
    const float* Whh0 = (const float*)d_in[4];
    const float* bih0 = (const float*)d_in[5];
    const float* bhh0 = (const float*)d_in[6];
    const float* Wih1 = (const float*)d_in[7];
    const float* Whh1 = (const float*)d_in[8];
    const float* bih1 = (const float*)d_in[9];
    const float* bhh1 = (const float*)d_in[10];
    const float* fcW  = (const float*)d_in[11];
    const float* fcb  = (const float*)d_in[12];
    float* out = (float*)d_out;

    cudaFuncSetAttribute(lstm_all_kernel,
                         cudaFuncAttributeMaxDynamicSharedMemorySize, SMEM_BYTES);
    lstm_all_kernel<<<NCTA, NTHR, SMEM_BYTES>>>(inp, h0, c0,
                                                Wih0, Whh0, bih0, bhh0,
                                                Wih1, Whh1, bih1, bhh1,
                                                fcW, fcb, out);
}